// round 13
// baseline (speedup 1.0000x reference)
#include <cuda_runtime.h>
#include <cuda_fp16.h>
#include <math.h>
#include <stdint.h>

#define B_ 4
#define T_ 2048
#define D_ 1024
#define M_ (B_*T_)

#define LDQK 2112               // padded row stride (halves) for qk buffer
#define LDS  2112               // padded row stride (halves) for scores buffer
#define LDVT 2112               // padded row stride (halves) for v^T buffer

#define NT 128                  // 4 warps per CTA
#define BM 128
#define BN 128
#define BK 32                   // halves per k-chunk (64 B)
#define LDB_S 80                // bytes per smem row
#define TILE_B (128*LDB_S)      // 10240 B per operand tile
#define STAGE_B (2*TILE_B)      // 20480 B
#define NSTAGE 3
#define SMEM_B (NSTAGE*STAGE_B) // 61440 B
#define GRID_P 304              // persistent CTAs (2 per SM, 152 SMs)

// ---------------- scratch ------------------------------------------------------
__device__ __half g_h  [M_*D_];
__device__ __half g_qk [(size_t)M_*LDQK];
__device__ __half g_vt [(size_t)B_*D_*LDVT];
__device__ __half g_s  [(size_t)B_*T_*LDS];
__device__ float  g_y  [M_*D_];
__device__ __half g_h2 [M_*D_];
__device__ __half g_m1 [M_*D_];
__device__ __half g_wqkt[2048*D_];
__device__ __half g_wvt[D_*D_];
__device__ __half g_w1t[D_*D_];
__device__ __half g_w2t[D_*D_];

// ---------------- helpers ------------------------------------------------------
__device__ __forceinline__ uint32_t smem_u32(const void* p) {
    uint32_t a;
    asm("{ .reg .u64 t; cvta.to.shared.u64 t, %1; cvt.u32.u64 %0, t; }" : "=r"(a) : "l"(p));
    return a;
}
__device__ __forceinline__ void cpa16u(uint32_t dst, const void* g) {
    asm volatile("cp.async.cg.shared.global [%0], [%1], 16;" :: "r"(dst), "l"(g));
}
#define CP_COMMIT() asm volatile("cp.async.commit_group;")
#define CP_WAIT1()  asm volatile("cp.async.wait_group 1;")

__device__ __forceinline__ void ldsm4(uint32_t& r0, uint32_t& r1, uint32_t& r2,
                                      uint32_t& r3, uint32_t a) {
    asm volatile("ldmatrix.sync.aligned.m8n8.x4.shared.b16 {%0,%1,%2,%3}, [%4];"
                 : "=r"(r0), "=r"(r1), "=r"(r2), "=r"(r3) : "r"(a));
}
__device__ __forceinline__ void mma_f16(float c[4], uint32_t a0, uint32_t a1,
                                        uint32_t a2, uint32_t a3,
                                        uint32_t b0, uint32_t b1) {
    asm volatile(
        "mma.sync.aligned.m16n8k16.row.col.f32.f16.f16.f32 "
        "{%0,%1,%2,%3}, {%4,%5,%6,%7}, {%8,%9}, {%0,%1,%2,%3};"
        : "+f"(c[0]), "+f"(c[1]), "+f"(c[2]), "+f"(c[3])
        : "r"(a0), "r"(a1), "r"(a2), "r"(a3), "r"(b0), "r"(b1));
}

// ---------------- fused prep: LN1 (blocks 0..M_-1) + weight transpose -----------
struct WT5 { const float* src[5]; __half* dst[5]; };
__global__ void prep_kernel(const float* __restrict__ x, const float* __restrict__ gamma,
                            const float* __restrict__ beta, __half* __restrict__ hout,
                            WT5 wt)
{
    __shared__ float sh[32 * 33];
    const int tid = threadIdx.x;
    if (blockIdx.x < M_) {
        const int row = blockIdx.x;
        const float4* x4 = (const float4*)(x + (size_t)row * D_);
        float4 v = x4[tid];
        float s  = v.x + v.y + v.z + v.w;
        float ss = v.x*v.x + v.y*v.y + v.z*v.z + v.w*v.w;
        #pragma unroll
        for (int o = 16; o; o >>= 1) {
            s  += __shfl_xor_sync(0xffffffffu, s, o);
            ss += __shfl_xor_sync(0xffffffffu, ss, o);
        }
        const int w = tid >> 5;
        if ((tid & 31) == 0) { sh[w] = s; sh[8 + w] = ss; }
        __syncthreads();
        s = 0.f; ss = 0.f;
        #pragma unroll
        for (int k = 0; k < 8; k++) { s += sh[k]; ss += sh[8 + k]; }
        const float mu  = s * (1.0f / D_);
        const float var = (ss - (float)D_ * mu * mu) * (1.0f / (float)(D_ - 1));
        const float cc  = mu * rsqrtf(var);
        __half2* o2 = (__half2*)(hout + (size_t)row * D_);
        const int j = tid * 4;
        o2[2*tid]   = __floats2half2_rn((v.x - cc) * gamma[j]   + beta[j],
                                        (v.y - cc) * gamma[j+1] + beta[j+1]);
        o2[2*tid+1] = __floats2half2_rn((v.z - cc) * gamma[j+2] + beta[j+2],
                                        (v.w - cc) * gamma[j+3] + beta[j+3]);
    } else {
        const int u   = blockIdx.x - M_;
        const int mi  = u >> 10;
        const int rem = u & 1023;
        const int byi = (rem >> 5) * 32;
        const int bxi = (rem & 31) * 32;
        const float* in = wt.src[mi];
        __half* out = wt.dst[mi];
        const float scale = (mi == 0) ? 0.03125f : 1.0f;
        const int tx = tid & 31;
        const int ty = tid >> 5;
        #pragma unroll
        for (int i = 0; i < 32; i += 8)
            sh[(ty + i) * 33 + tx] = in[(size_t)(byi + ty + i) * D_ + bxi + tx] * scale;
        __syncthreads();
        #pragma unroll
        for (int i = 0; i < 32; i += 8)
            out[(size_t)(bxi + ty + i) * D_ + byi + tx] = __float2half_rn(sh[tx * 33 + ty + i]);
    }
}

// ---------------- LayerNorm kernel (for LN2), half output -----------------------
__global__ void ln_kernel(const float* __restrict__ x, const float* __restrict__ gamma,
                          const float* __restrict__ beta, __half* __restrict__ out)
{
    const int row = blockIdx.x;
    const float4* x4 = (const float4*)(x + (size_t)row * D_);
    const int tid = threadIdx.x;
    float4 v = x4[tid];
    float s  = v.x + v.y + v.z + v.w;
    float ss = v.x*v.x + v.y*v.y + v.z*v.z + v.w*v.w;
    #pragma unroll
    for (int o = 16; o; o >>= 1) {
        s  += __shfl_xor_sync(0xffffffffu, s, o);
        ss += __shfl_xor_sync(0xffffffffu, ss, o);
    }
    __shared__ float sh_s[8], sh_ss[8];
    const int w = tid >> 5;
    if ((tid & 31) == 0) { sh_s[w] = s; sh_ss[w] = ss; }
    __syncthreads();
    s = 0.f; ss = 0.f;
    #pragma unroll
    for (int k = 0; k < 8; k++) { s += sh_s[k]; ss += sh_ss[k]; }
    const float mu  = s * (1.0f / D_);
    const float var = (ss - (float)D_ * mu * mu) * (1.0f / (float)(D_ - 1));
    const float c   = mu * rsqrtf(var);
    __half2* o2 = (__half2*)(out + (size_t)row * D_);
    const int j = tid * 4;
    o2[2*tid]   = __floats2half2_rn((v.x - c) * gamma[j]   + beta[j],
                                    (v.y - c) * gamma[j+1] + beta[j+1]);
    o2[2*tid+1] = __floats2half2_rn((v.z - c) * gamma[j+2] + beta[j+2],
                                    (v.w - c) * gamma[j+3] + beta[j+3]);
}

// ---------------- register-cached causal softmax (padded stride) ----------------
__global__ void softmax_kernel(__half* __restrict__ S)
{
    const int row = blockIdx.x;
    const int b = row >> 11;
    const int q = row & (T_ - 1);
    __half2* r2 = (__half2*)(S + (size_t)b * T_ * LDS + (size_t)q * LDS);
    const int n = q + 1;
    const int nh2 = (n + 1) >> 1;
    const int pad2 = (((q >> 7) + 1) << 7) >> 1;
    const int tid = threadIdx.x;

    float2 ex[4];
    float m = -1e30f;
    #pragma unroll
    for (int j = 0; j < 4; j++) {
        const int i = tid + j * 256;
        float2 v = make_float2(-1e30f, -1e30f);
        if (i < nh2) {
            __half2 h = r2[i];
            v.x = __half2float(__low2half(h));
            v.y = (2 * i + 1 < n) ? __half2float(__high2half(h)) : -1e30f;
        }
        ex[j] = v;
        m = fmaxf(m, fmaxf(v.x, v.y));
    }
    #pragma unroll
    for (int o = 16; o; o >>= 1) m = fmaxf(m, __shfl_xor_sync(0xffffffffu, m, o));
    __shared__ float shm[8], shs[8];
    const int w = tid >> 5;
    if ((tid & 31) == 0) shm[w] = m;
    __syncthreads();
    m = shm[0];
    #pragma unroll
    for (int i = 1; i < 8; i++) m = fmaxf(m, shm[i]);

    float s = 0.f;
    #pragma unroll
    for (int j = 0; j < 4; j++) {
        float e0 = (ex[j].x > -1e29f) ? __expf(ex[j].x - m) : 0.f;
        float e1 = (ex[j].y > -1e29f) ? __expf(ex[j].y - m) : 0.f;
        ex[j].x = e0; ex[j].y = e1;
        s += e0 + e1;
    }
    #pragma unroll
    for (int o = 16; o; o >>= 1) s += __shfl_xor_sync(0xffffffffu, s, o);
    if ((tid & 31) == 0) shs[w] = s;
    __syncthreads();
    s = 0.f;
    #pragma unroll
    for (int i = 0; i < 8; i++) s += shs[i];
    const float inv = 1.0f / s;

    #pragma unroll
    for (int j = 0; j < 4; j++) {
        const int i = tid + j * 256;
        if (i < pad2) {
            float2 o = (i < nh2) ? make_float2(ex[j].x * inv, ex[j].y * inv)
                                 : make_float2(0.f, 0.f);
            r2[i] = __floats2half2_rn(o.x, o.y);
        }
    }
}

// ---------------- persistent fp16 TN GEMM: 4 warps, 64x64 warp tiles -------------
// EPI 0: half(acc); 1: half(relu(acc+bias)); 3: float acc+resid; 4: float acc+bias+resid
// MODE 0: plain flattened (z,y,x); 1: scores lower-triangle;
// MODE 2: AV (k bound at bm+128), cost-sorted heavy-first schedule
template<int EPI, int MODE>
__global__ __launch_bounds__(NT, 2)
void hgemm(const __half* __restrict__ A0, const __half* __restrict__ B0, void* Cv,
           const float* __restrict__ bias, const float* __restrict__ resid0,
           int lda, int ldb, int K, int ldc,
           size_t sA, size_t sB, size_t sC,
           int ntx, int nty, int ntz)
{
    extern __shared__ char smc[];
    const uint32_t sb = smem_u32(smc);

    const int tid  = threadIdx.x;
    const int lane = tid & 31;
    const int warp = tid >> 5;
    const int g    = lane >> 2;
    const int tq   = lane & 3;
    const int wm   = (warp >> 1) * 64;
    const int wn   = (warp & 1) * 64;
    const int lrow = tid >> 2;
    const int lcc  = tid & 3;

    const uint32_t a_l = (uint32_t)(wm + (lane & 15)) * LDB_S + (uint32_t)(lane >> 4) * 16;
    const uint32_t b_l = (uint32_t)(wn + (lane & 7) + ((lane >> 4) & 1) * 8) * LDB_S
                       + (uint32_t)((lane >> 3) & 1) * 16;

    const int tri = nty * (nty + 1) / 2;
    const int ntiles = (MODE == 1) ? ntz * tri : ntx * nty * ntz;
    const int nsteps = (ntiles + GRID_P - 1) / GRID_P;

    for (int s = 0; s < nsteps; s++) {
        int tx, ty, tz;
        if (MODE == 2) {
            int r = (s == 0) ? (int)blockIdx.x : (2 * GRID_P - 1 - (int)blockIdx.x);
            if (r >= ntiles) continue;
            ty = nty - 1 - r / (ntx * ntz);
            const int rem = r % (ntx * ntz);
            tz = rem / ntx;
            tx = rem % ntx;
        } else if (MODE == 1) {
            const int tile = s * GRID_P + blockIdx.x;
            if (tile >= ntiles) continue;
            tz = tile / tri;
            int t = tile - tz * tri;
            ty = 0;
            while (t >= ty + 1) { t -= ty + 1; ty++; }
            tx = t;
        } else {
            const int tile = s * GRID_P + blockIdx.x;
            if (tile >= ntiles) continue;
            tx = tile % ntx;
            ty = (tile / ntx) % nty;
            tz = tile / (ntx * nty);
        }
        const int bm = ty * BM;
        const int bn = tx * BN;

        const __half* A  = A0 + (size_t)tz * sA + (size_t)bm * lda;
        const __half* Bm = B0 + (size_t)tz * sB + (size_t)bn * ldb;
        __half* Ch = (__half*)Cv + (size_t)tz * sC;
        float*  Cf = (float*)Cv  + (size_t)tz * sC;
        const float* resid = resid0 ? resid0 + (size_t)tz * sC : resid0;

        float c[4][8][4];
        #pragma unroll
        for (int i = 0; i < 4; i++)
            #pragma unroll
            for (int j = 0; j < 8; j++)
                #pragma unroll
                for (int l = 0; l < 4; l++) c[i][j][l] = 0.f;

        const int nt = (MODE == 2) ? (bm / BK + 4) : (K / BK);

        __syncthreads();

        auto load_stage = [&](int buf, int t) {
            const int k0 = t * BK;
            const uint32_t base = sb + buf * STAGE_B;
            #pragma unroll
            for (int p = 0; p < 4; p++) {
                const int r = lrow + p * 32;
                const uint32_t da = base + r * LDB_S + lcc * 16;
                cpa16u(da, A + (size_t)r * lda + k0 + lcc * 8);
                cpa16u(da + TILE_B, Bm + (size_t)r * ldb + k0 + lcc * 8);
            }
        };

        load_stage(0, 0); CP_COMMIT();
        load_stage(1, 1); CP_COMMIT();

        for (int t = 0; t < nt; t++) {
            CP_WAIT1();
            __syncthreads();
            if (t + 2 < nt) load_stage((t + 2) % NSTAGE, t + 2);
            CP_COMMIT();

            const uint32_t sbase = sb + (t % NSTAGE) * STAGE_B;
            const uint32_t aaddr = sbase + a_l;
            const uint32_t baddr = sbase + TILE_B + b_l;

            #pragma unroll
            for (int s8 = 0; s8 < 2; s8++) {
                const uint32_t ko = s8 * 32;
                uint32_t af[4][4], bf[4][4];
                #pragma unroll
                for (int mt = 0; mt < 4; mt++)
                    ldsm4(af[mt][0], af[mt][1], af[mt][2], af[mt][3],
                          aaddr + mt * (16 * LDB_S) + ko);
                #pragma unroll
                for (int np = 0; np < 4; np++)
                    ldsm4(bf[np][0], bf[np][1], bf[np][2], bf[np][3],
                          baddr + np * (16 * LDB_S) + ko);
                #pragma unroll
                for (int mt = 0; mt < 4; mt++)
                    #pragma unroll
                    for (int ntl = 0; ntl < 8; ntl++)
                        mma_f16(c[mt][ntl],
                                af[mt][0], af[mt][1], af[mt][2], af[mt][3],
                                bf[ntl >> 1][(ntl & 1) * 2], bf[ntl >> 1][(ntl & 1) * 2 + 1]);
            }
        }

        // ---------------- epilogue ----------------
        #pragma unroll
        for (int mt = 0; mt < 4; mt++) {
            #pragma unroll
            for (int ntl = 0; ntl < 8; ntl++) {
                const int col = bn + wn + ntl * 8 + 2 * tq;
                float b0 = 0.f, b1 = 0.f;
                if (EPI == 1 || EPI == 4) { b0 = bias[col]; b1 = bias[col + 1]; }
                #pragma unroll
                for (int h = 0; h < 2; h++) {
                    const int row = bm + wm + mt * 16 + g + h * 8;
                    float v0 = c[mt][ntl][2 * h], v1 = c[mt][ntl][2 * h + 1];
                    if (EPI == 0) {
                        *(__half2*)&Ch[(size_t)row * ldc + col] = __floats2half2_rn(v0, v1);
                    } else if (EPI == 1) {
                        v0 = fmaxf(v0 + b0, 0.f);
                        v1 = fmaxf(v1 + b1, 0.f);
                        *(__half2*)&Ch[(size_t)row * ldc + col] = __floats2half2_rn(v0, v1);
                    } else if (EPI == 3) {
                        float2 rv = *(const float2*)&resid[(size_t)row * ldc + col];
                        float2 o; o.x = v0 + rv.x; o.y = v1 + rv.y;
                        *(float2*)&Cf[(size_t)row * ldc + col] = o;
                    } else {
                        float2 rv = *(const float2*)&resid[(size_t)row * ldc + col];
                        float2 o; o.x = v0 + b0 + rv.x; o.y = v1 + b1 + rv.y;
                        *(float2*)&Cf[(size_t)row * ldc + col] = o;
                    }
                }
            }
        }
    }
}

// ---------------- launch --------------------------------------------------------
extern "C" void kernel_launch(void* const* d_in, const int* in_sizes, int n_in,
                              void* d_out, int out_size)
{
    const float* x   = (const float*)d_in[0];
    const float* g1  = (const float*)d_in[1];
    const float* be1 = (const float*)d_in[2];
    const float* wq  = (const float*)d_in[3];
    const float* wk  = (const float*)d_in[4];
    const float* wv  = (const float*)d_in[5];
    const float* g2  = (const float*)d_in[6];
    const float* be2 = (const float*)d_in[7];
    const float* W1  = (const float*)d_in[8];
    const float* b1  = (const float*)d_in[9];
    const float* W2  = (const float*)d_in[10];
    const float* b2  = (const float*)d_in[11];
    float* out = (float*)d_out;

    __half *p_h, *p_qk, *p_vt, *p_s, *p_h2, *p_m1;
    __half *p_wqkt, *p_wvt, *p_w1t, *p_w2t;
    float *p_y;
    cudaGetSymbolAddress((void**)&p_h,    g_h);
    cudaGetSymbolAddress((void**)&p_qk,   g_qk);
    cudaGetSymbolAddress((void**)&p_vt,   g_vt);
    cudaGetSymbolAddress((void**)&p_s,    g_s);
    cudaGetSymbolAddress((void**)&p_y,    g_y);
    cudaGetSymbolAddress((void**)&p_h2,   g_h2);
    cudaGetSymbolAddress((void**)&p_m1,   g_m1);
    cudaGetSymbolAddress((void**)&p_wqkt, g_wqkt);
    cudaGetSymbolAddress((void**)&p_wvt,  g_wvt);
    cudaGetSymbolAddress((void**)&p_w1t,  g_w1t);
    cudaGetSymbolAddress((void**)&p_w2t,  g_w2t);

    cudaFuncSetAttribute(hgemm<0,0>, cudaFuncAttributeMaxDynamicSharedMemorySize, SMEM_B);
    cudaFuncSetAttribute(hgemm<1,0>, cudaFuncAttributeMaxDynamicSharedMemorySize, SMEM_B);
    cudaFuncSetAttribute(hgemm<4,0>, cudaFuncAttributeMaxDynamicSharedMemorySize, SMEM_B);
    cudaFuncSetAttribute(hgemm<0,1>, cudaFuncAttributeMaxDynamicSharedMemorySize, SMEM_B);
    cudaFuncSetAttribute(hgemm<3,2>, cudaFuncAttributeMaxDynamicSharedMemorySize, SMEM_B);

    WT5 wt;
    wt.src[0] = wq; wt.dst[0] = p_wqkt;
    wt.src[1] = wk; wt.dst[1] = p_wqkt + (size_t)1024 * D_;
    wt.src[2] = wv; wt.dst[2] = p_wvt;
    wt.src[3] = W1; wt.dst[3] = p_w1t;
    wt.src[4] = W2; wt.dst[4] = p_w2t;

    // fused LN1 + weight transpose
    prep_kernel<<<M_ + 5 * 1024, 256>>>(x, g1, be1, p_h, wt);

    // qk = h @ [wq/32 | wk]   (N=2048, padded ldc)
    hgemm<0,0><<<GRID_P, NT, SMEM_B>>>(p_h, p_wqkt, p_qk, nullptr, nullptr,
                                       D_, D_, D_, LDQK, 0, 0, 0, 16, 64, 1);
    // vt[b][d][t] = wvt[d][:] . h[b*T+t][:]   (padded ldc)
    hgemm<0,0><<<GRID_P, NT, SMEM_B>>>(p_wvt, p_h, p_vt, nullptr, nullptr,
                                       D_, D_, D_, LDVT,
                                       0, (size_t)T_*D_, (size_t)D_*LDVT, 16, 8, 4);
    // scores (pre-scaled q): lower triangle only, padded operand strides
    hgemm<0,1><<<GRID_P, NT, SMEM_B>>>(p_qk, p_qk + 1024, p_s, nullptr, nullptr,
                                       LDQK, LDQK, D_, LDS,
                                       (size_t)T_*LDQK, (size_t)T_*LDQK, (size_t)T_*LDS,
                                       16, 16, 4);
    softmax_kernel<<<M_, 256>>>(p_s);
    // y = P @ V^T + x  (cost-sorted schedule, padded operand strides)
    hgemm<3,2><<<GRID_P, NT, SMEM_B>>>(p_s, p_vt, p_y, nullptr, x,
                                       LDS, LDVT, T_, D_,
                                       (size_t)T_*LDS, (size_t)D_*LDVT, (size_t)T_*D_,
                                       8, 16, 4);
    ln_kernel<<<M_, 256>>>(p_y, g2, be2, p_h2);
    hgemm<1,0><<<GRID_P, NT, SMEM_B>>>(p_h2, p_w1t, p_m1, b1, nullptr,
                                       D_, D_, D_, D_, 0, 0, 0, 8, 64, 1);
    hgemm<4,0><<<GRID_P, NT, SMEM_B>>>(p_m1, p_w2t, out, b2, p_y,
                                       D_, D_, D_, D_, 0, 0, 0, 8, 64, 1);
}

// round 14
// speedup vs baseline: 1.0177x; 1.0177x over previous
#include <cuda_runtime.h>
#include <cuda_fp16.h>
#include <math.h>
#include <stdint.h>

#define B_ 4
#define T_ 2048
#define D_ 1024
#define M_ (B_*T_)

#define NT 128                  // 4 warps per CTA
#define BM 128
#define BN 128
#define BK 32                   // halves per k-chunk (64 B)
#define LDB_S 80                // bytes per smem row
#define TILE_B (128*LDB_S)      // 10240 B per operand tile
#define STAGE_B (2*TILE_B)      // 20480 B
#define NSTAGE 3
#define SMEM_B (NSTAGE*STAGE_B) // 61440 B
#define GRID_P 304              // persistent CTAs (2 per SM, 152 SMs)

// ---------------- scratch ------------------------------------------------------
__device__ __half g_h  [M_*D_];
__device__ __half g_qk [(size_t)M_*2048];
__device__ __half g_vt [(size_t)B_*D_*T_];
__device__ __half g_s  [(size_t)B_*T_*T_];
__device__ __half g_y  [M_*D_];          // fp16 now (was fp32)
__device__ __half g_h2 [M_*D_];
__device__ __half g_m1 [M_*D_];
__device__ __half g_wqkt[2048*D_];
__device__ __half g_wvt[D_*D_];
__device__ __half g_w1t[D_*D_];
__device__ __half g_w2t[D_*D_];

// ---------------- helpers ------------------------------------------------------
__device__ __forceinline__ uint32_t smem_u32(const void* p) {
    uint32_t a;
    asm("{ .reg .u64 t; cvta.to.shared.u64 t, %1; cvt.u32.u64 %0, t; }" : "=r"(a) : "l"(p));
    return a;
}
__device__ __forceinline__ void cpa16u(uint32_t dst, const void* g) {
    asm volatile("cp.async.cg.shared.global [%0], [%1], 16;" :: "r"(dst), "l"(g));
}
#define CP_COMMIT() asm volatile("cp.async.commit_group;")
#define CP_WAIT1()  asm volatile("cp.async.wait_group 1;")

__device__ __forceinline__ void ldsm4(uint32_t& r0, uint32_t& r1, uint32_t& r2,
                                      uint32_t& r3, uint32_t a) {
    asm volatile("ldmatrix.sync.aligned.m8n8.x4.shared.b16 {%0,%1,%2,%3}, [%4];"
                 : "=r"(r0), "=r"(r1), "=r"(r2), "=r"(r3) : "r"(a));
}
__device__ __forceinline__ void mma_f16(float c[4], uint32_t a0, uint32_t a1,
                                        uint32_t a2, uint32_t a3,
                                        uint32_t b0, uint32_t b1) {
    asm volatile(
        "mma.sync.aligned.m16n8k16.row.col.f32.f16.f16.f32 "
        "{%0,%1,%2,%3}, {%4,%5,%6,%7}, {%8,%9}, {%0,%1,%2,%3};"
        : "+f"(c[0]), "+f"(c[1]), "+f"(c[2]), "+f"(c[3])
        : "r"(a0), "r"(a1), "r"(a2), "r"(a3), "r"(b0), "r"(b1));
}

// ---------------- fused prep: LN1 (blocks 0..M_-1) + weight transpose -----------
struct WT5 { const float* src[5]; __half* dst[5]; };
__global__ void prep_kernel(const float* __restrict__ x, const float* __restrict__ gamma,
                            const float* __restrict__ beta, __half* __restrict__ hout,
                            WT5 wt)
{
    __shared__ float sh[32 * 33];
    const int tid = threadIdx.x;
    if (blockIdx.x < M_) {
        const int row = blockIdx.x;
        const float4* x4 = (const float4*)(x + (size_t)row * D_);
        float4 v = x4[tid];
        float s  = v.x + v.y + v.z + v.w;
        float ss = v.x*v.x + v.y*v.y + v.z*v.z + v.w*v.w;
        #pragma unroll
        for (int o = 16; o; o >>= 1) {
            s  += __shfl_xor_sync(0xffffffffu, s, o);
            ss += __shfl_xor_sync(0xffffffffu, ss, o);
        }
        const int w = tid >> 5;
        if ((tid & 31) == 0) { sh[w] = s; sh[8 + w] = ss; }
        __syncthreads();
        s = 0.f; ss = 0.f;
        #pragma unroll
        for (int k = 0; k < 8; k++) { s += sh[k]; ss += sh[8 + k]; }
        const float mu  = s * (1.0f / D_);
        const float var = (ss - (float)D_ * mu * mu) * (1.0f / (float)(D_ - 1));
        const float cc  = mu * rsqrtf(var);
        __half2* o2 = (__half2*)(hout + (size_t)row * D_);
        const int j = tid * 4;
        o2[2*tid]   = __floats2half2_rn((v.x - cc) * gamma[j]   + beta[j],
                                        (v.y - cc) * gamma[j+1] + beta[j+1]);
        o2[2*tid+1] = __floats2half2_rn((v.z - cc) * gamma[j+2] + beta[j+2],
                                        (v.w - cc) * gamma[j+3] + beta[j+3]);
    } else {
        const int u   = blockIdx.x - M_;
        const int mi  = u >> 10;
        const int rem = u & 1023;
        const int byi = (rem >> 5) * 32;
        const int bxi = (rem & 31) * 32;
        const float* in = wt.src[mi];
        __half* out = wt.dst[mi];
        const float scale = (mi == 0) ? 0.03125f : 1.0f;
        const int tx = tid & 31;
        const int ty = tid >> 5;
        #pragma unroll
        for (int i = 0; i < 32; i += 8)
            sh[(ty + i) * 33 + tx] = in[(size_t)(byi + ty + i) * D_ + bxi + tx] * scale;
        __syncthreads();
        #pragma unroll
        for (int i = 0; i < 32; i += 8)
            out[(size_t)(bxi + ty + i) * D_ + byi + tx] = __float2half_rn(sh[tx * 33 + ty + i]);
    }
}

// ---------------- LayerNorm on half input (LN2), half output --------------------
__global__ void ln_half_kernel(const __half* __restrict__ y, const float* __restrict__ gamma,
                               const float* __restrict__ beta, __half* __restrict__ out)
{
    const int row = blockIdx.x;
    const __half2* y2 = (const __half2*)(y + (size_t)row * D_);
    const int tid = threadIdx.x;
    __half2 h0 = y2[2*tid], h1 = y2[2*tid+1];
    float v0 = __half2float(__low2half(h0)),  v1 = __half2float(__high2half(h0));
    float v2 = __half2float(__low2half(h1)),  v3 = __half2float(__high2half(h1));
    float s  = v0 + v1 + v2 + v3;
    float ss = v0*v0 + v1*v1 + v2*v2 + v3*v3;
    #pragma unroll
    for (int o = 16; o; o >>= 1) {
        s  += __shfl_xor_sync(0xffffffffu, s, o);
        ss += __shfl_xor_sync(0xffffffffu, ss, o);
    }
    __shared__ float sh_s[8], sh_ss[8];
    const int w = tid >> 5;
    if ((tid & 31) == 0) { sh_s[w] = s; sh_ss[w] = ss; }
    __syncthreads();
    s = 0.f; ss = 0.f;
    #pragma unroll
    for (int k = 0; k < 8; k++) { s += sh_s[k]; ss += sh_ss[k]; }
    const float mu  = s * (1.0f / D_);
    const float var = (ss - (float)D_ * mu * mu) * (1.0f / (float)(D_ - 1));
    const float c   = mu * rsqrtf(var);
    __half2* o2 = (__half2*)(out + (size_t)row * D_);
    const int j = tid * 4;
    o2[2*tid]   = __floats2half2_rn((v0 - c) * gamma[j]   + beta[j],
                                    (v1 - c) * gamma[j+1] + beta[j+1]);
    o2[2*tid+1] = __floats2half2_rn((v2 - c) * gamma[j+2] + beta[j+2],
                                    (v3 - c) * gamma[j+3] + beta[j+3]);
}

// ---------------- register-cached causal softmax (1 read + 1 write) -------------
__global__ void softmax_kernel(__half* __restrict__ S)
{
    const int row = blockIdx.x;
    const int b = row >> 11;
    const int q = row & (T_ - 1);
    __half2* r2 = (__half2*)(S + (size_t)b * T_ * T_ + (size_t)q * T_);
    const int n = q + 1;
    const int nh2 = (n + 1) >> 1;
    const int pad2 = (((q >> 7) + 1) << 7) >> 1;
    const int tid = threadIdx.x;

    float2 ex[4];
    float m = -1e30f;
    #pragma unroll
    for (int j = 0; j < 4; j++) {
        const int i = tid + j * 256;
        float2 v = make_float2(-1e30f, -1e30f);
        if (i < nh2) {
            __half2 h = r2[i];
            v.x = __half2float(__low2half(h));
            v.y = (2 * i + 1 < n) ? __half2float(__high2half(h)) : -1e30f;
        }
        ex[j] = v;
        m = fmaxf(m, fmaxf(v.x, v.y));
    }
    #pragma unroll
    for (int o = 16; o; o >>= 1) m = fmaxf(m, __shfl_xor_sync(0xffffffffu, m, o));
    __shared__ float shm[8], shs[8];
    const int w = tid >> 5;
    if ((tid & 31) == 0) shm[w] = m;
    __syncthreads();
    m = shm[0];
    #pragma unroll
    for (int i = 1; i < 8; i++) m = fmaxf(m, shm[i]);

    float s = 0.f;
    #pragma unroll
    for (int j = 0; j < 4; j++) {
        float e0 = (ex[j].x > -1e29f) ? __expf(ex[j].x - m) : 0.f;
        float e1 = (ex[j].y > -1e29f) ? __expf(ex[j].y - m) : 0.f;
        ex[j].x = e0; ex[j].y = e1;
        s += e0 + e1;
    }
    #pragma unroll
    for (int o = 16; o; o >>= 1) s += __shfl_xor_sync(0xffffffffu, s, o);
    if ((tid & 31) == 0) shs[w] = s;
    __syncthreads();
    s = 0.f;
    #pragma unroll
    for (int i = 0; i < 8; i++) s += shs[i];
    const float inv = 1.0f / s;

    #pragma unroll
    for (int j = 0; j < 4; j++) {
        const int i = tid + j * 256;
        if (i < pad2) {
            float2 o = (i < nh2) ? make_float2(ex[j].x * inv, ex[j].y * inv)
                                 : make_float2(0.f, 0.f);
            r2[i] = __floats2half2_rn(o.x, o.y);
        }
    }
}

// ---------------- persistent fp16 TN GEMM: 4 warps, 64x64 warp tiles -------------
// EPI 0: half(acc); 1: half(relu(acc+bias));
// EPI 3: half(acc + fp32 resid)            [AV: y = P@V^T + x, half out]
// EPI 4: float acc + bias + half resid     [mlp2: out = m1@W2 + b2 + y]
// MODE 0: plain flattened (z,y,x); 1: scores lower-triangle;
// MODE 2: AV (k bound at bm+128), cost-sorted heavy-first schedule
template<int EPI, int MODE>
__global__ __launch_bounds__(NT, 2)
void hgemm(const __half* __restrict__ A0, const __half* __restrict__ B0, void* Cv,
           const float* __restrict__ bias, const void* __restrict__ resid0,
           int lda, int ldb, int K, int N,
           size_t sA, size_t sB, size_t sC,
           int ntx, int nty, int ntz)
{
    extern __shared__ char smc[];
    const uint32_t sb = smem_u32(smc);

    const int tid  = threadIdx.x;
    const int lane = tid & 31;
    const int warp = tid >> 5;
    const int g    = lane >> 2;
    const int tq   = lane & 3;
    const int wm   = (warp >> 1) * 64;
    const int wn   = (warp & 1) * 64;
    const int lrow = tid >> 2;
    const int lcc  = tid & 3;

    const uint32_t a_l = (uint32_t)(wm + (lane & 15)) * LDB_S + (uint32_t)(lane >> 4) * 16;
    const uint32_t b_l = (uint32_t)(wn + (lane & 7) + ((lane >> 4) & 1) * 8) * LDB_S
                       + (uint32_t)((lane >> 3) & 1) * 16;

    const int tri = nty * (nty + 1) / 2;
    const int ntiles = (MODE == 1) ? ntz * tri : ntx * nty * ntz;
    const int nsteps = (ntiles + GRID_P - 1) / GRID_P;

    for (int s = 0; s < nsteps; s++) {
        int tx, ty, tz;
        if (MODE == 2) {
            int r = (s == 0) ? (int)blockIdx.x : (2 * GRID_P - 1 - (int)blockIdx.x);
            if (r >= ntiles) continue;
            ty = nty - 1 - r / (ntx * ntz);
            const int rem = r % (ntx * ntz);
            tz = rem / ntx;
            tx = rem % ntx;
        } else if (MODE == 1) {
            const int tile = s * GRID_P + blockIdx.x;
            if (tile >= ntiles) continue;
            tz = tile / tri;
            int t = tile - tz * tri;
            ty = 0;
            while (t >= ty + 1) { t -= ty + 1; ty++; }
            tx = t;
        } else {
            const int tile = s * GRID_P + blockIdx.x;
            if (tile >= ntiles) continue;
            tx = tile % ntx;
            ty = (tile / ntx) % nty;
            tz = tile / (ntx * nty);
        }
        const int bm = ty * BM;
        const int bn = tx * BN;

        const __half* A  = A0 + (size_t)tz * sA + (size_t)bm * lda;
        const __half* Bm = B0 + (size_t)tz * sB + (size_t)bn * ldb;
        __half* Ch = (__half*)Cv + (size_t)tz * sC;
        float*  Cf = (float*)Cv  + (size_t)tz * sC;
        const float*  residf = resid0 ? (const float*)resid0  + (size_t)tz * sC : nullptr;
        const __half* residh = resid0 ? (const __half*)resid0 + (size_t)tz * sC : nullptr;

        float c[4][8][4];
        #pragma unroll
        for (int i = 0; i < 4; i++)
            #pragma unroll
            for (int j = 0; j < 8; j++)
                #pragma unroll
                for (int l = 0; l < 4; l++) c[i][j][l] = 0.f;

        const int nt = (MODE == 2) ? (bm / BK + 4) : (K / BK);

        __syncthreads();

        auto load_stage = [&](int buf, int t) {
            const int k0 = t * BK;
            const uint32_t base = sb + buf * STAGE_B;
            #pragma unroll
            for (int p = 0; p < 4; p++) {
                const int r = lrow + p * 32;
                const uint32_t da = base + r * LDB_S + lcc * 16;
                cpa16u(da, A + (size_t)r * lda + k0 + lcc * 8);
                cpa16u(da + TILE_B, Bm + (size_t)r * ldb + k0 + lcc * 8);
            }
        };

        load_stage(0, 0); CP_COMMIT();
        load_stage(1, 1); CP_COMMIT();

        for (int t = 0; t < nt; t++) {
            CP_WAIT1();
            __syncthreads();
            if (t + 2 < nt) load_stage((t + 2) % NSTAGE, t + 2);
            CP_COMMIT();

            const uint32_t sbase = sb + (t % NSTAGE) * STAGE_B;
            const uint32_t aaddr = sbase + a_l;
            const uint32_t baddr = sbase + TILE_B + b_l;

            #pragma unroll
            for (int s8 = 0; s8 < 2; s8++) {
                const uint32_t ko = s8 * 32;
                uint32_t af[4][4], bf[4][4];
                #pragma unroll
                for (int mt = 0; mt < 4; mt++)
                    ldsm4(af[mt][0], af[mt][1], af[mt][2], af[mt][3],
                          aaddr + mt * (16 * LDB_S) + ko);
                #pragma unroll
                for (int np = 0; np < 4; np++)
                    ldsm4(bf[np][0], bf[np][1], bf[np][2], bf[np][3],
                          baddr + np * (16 * LDB_S) + ko);
                #pragma unroll
                for (int mt = 0; mt < 4; mt++)
                    #pragma unroll
                    for (int ntl = 0; ntl < 8; ntl++)
                        mma_f16(c[mt][ntl],
                                af[mt][0], af[mt][1], af[mt][2], af[mt][3],
                                bf[ntl >> 1][(ntl & 1) * 2], bf[ntl >> 1][(ntl & 1) * 2 + 1]);
            }
        }

        // ---------------- epilogue ----------------
        #pragma unroll
        for (int mt = 0; mt < 4; mt++) {
            #pragma unroll
            for (int ntl = 0; ntl < 8; ntl++) {
                const int col = bn + wn + ntl * 8 + 2 * tq;
                float b0 = 0.f, b1 = 0.f;
                if (EPI == 1 || EPI == 4) { b0 = bias[col]; b1 = bias[col + 1]; }
                #pragma unroll
                for (int h = 0; h < 2; h++) {
                    const int row = bm + wm + mt * 16 + g + h * 8;
                    float v0 = c[mt][ntl][2 * h], v1 = c[mt][ntl][2 * h + 1];
                    if (EPI == 0) {
                        *(__half2*)&Ch[(size_t)row * N + col] = __floats2half2_rn(v0, v1);
                    } else if (EPI == 1) {
                        v0 = fmaxf(v0 + b0, 0.f);
                        v1 = fmaxf(v1 + b1, 0.f);
                        *(__half2*)&Ch[(size_t)row * N + col] = __floats2half2_rn(v0, v1);
                    } else if (EPI == 3) {
                        float2 rv = *(const float2*)&residf[(size_t)row * N + col];
                        *(__half2*)&Ch[(size_t)row * N + col] =
                            __floats2half2_rn(v0 + rv.x, v1 + rv.y);
                    } else {
                        __half2 rh = *(const __half2*)&residh[(size_t)row * N + col];
                        float2 o;
                        o.x = v0 + b0 + __half2float(__low2half(rh));
                        o.y = v1 + b1 + __half2float(__high2half(rh));
                        *(float2*)&Cf[(size_t)row * N + col] = o;
                    }
                }
            }
        }
    }
}

// ---------------- launch --------------------------------------------------------
extern "C" void kernel_launch(void* const* d_in, const int* in_sizes, int n_in,
                              void* d_out, int out_size)
{
    const float* x   = (const float*)d_in[0];
    const float* g1  = (const float*)d_in[1];
    const float* be1 = (const float*)d_in[2];
    const float* wq  = (const float*)d_in[3];
    const float* wk  = (const float*)d_in[4];
    const float* wv  = (const float*)d_in[5];
    const float* g2  = (const float*)d_in[6];
    const float* be2 = (const float*)d_in[7];
    const float* W1  = (const float*)d_in[8];
    const float* b1  = (const float*)d_in[9];
    const float* W2  = (const float*)d_in[10];
    const float* b2  = (const float*)d_in[11];
    float* out = (float*)d_out;

    __half *p_h, *p_qk, *p_vt, *p_s, *p_y, *p_h2, *p_m1;
    __half *p_wqkt, *p_wvt, *p_w1t, *p_w2t;
    cudaGetSymbolAddress((void**)&p_h,    g_h);
    cudaGetSymbolAddress((void**)&p_qk,   g_qk);
    cudaGetSymbolAddress((void**)&p_vt,   g_vt);
    cudaGetSymbolAddress((void**)&p_s,    g_s);
    cudaGetSymbolAddress((void**)&p_y,    g_y);
    cudaGetSymbolAddress((void**)&p_h2,   g_h2);
    cudaGetSymbolAddress((void**)&p_m1,   g_m1);
    cudaGetSymbolAddress((void**)&p_wqkt, g_wqkt);
    cudaGetSymbolAddress((void**)&p_wvt,  g_wvt);
    cudaGetSymbolAddress((void**)&p_w1t,  g_w1t);
    cudaGetSymbolAddress((void**)&p_w2t,  g_w2t);

    cudaFuncSetAttribute(hgemm<0,0>, cudaFuncAttributeMaxDynamicSharedMemorySize, SMEM_B);
    cudaFuncSetAttribute(hgemm<1,0>, cudaFuncAttributeMaxDynamicSharedMemorySize, SMEM_B);
    cudaFuncSetAttribute(hgemm<4,0>, cudaFuncAttributeMaxDynamicSharedMemorySize, SMEM_B);
    cudaFuncSetAttribute(hgemm<0,1>, cudaFuncAttributeMaxDynamicSharedMemorySize, SMEM_B);
    cudaFuncSetAttribute(hgemm<3,2>, cudaFuncAttributeMaxDynamicSharedMemorySize, SMEM_B);

    WT5 wt;
    wt.src[0] = wq; wt.dst[0] = p_wqkt;
    wt.src[1] = wk; wt.dst[1] = p_wqkt + (size_t)1024 * D_;
    wt.src[2] = wv; wt.dst[2] = p_wvt;
    wt.src[3] = W1; wt.dst[3] = p_w1t;
    wt.src[4] = W2; wt.dst[4] = p_w2t;

    // fused LN1 + weight transpose
    prep_kernel<<<M_ + 5 * 1024, 256>>>(x, g1, be1, p_h, wt);

    // qk = h @ [wq/32 | wk]   (N=2048)
    hgemm<0,0><<<GRID_P, NT, SMEM_B>>>(p_h, p_wqkt, p_qk, nullptr, nullptr,
                                       D_, D_, D_, 2048, 0, 0, 0, 16, 64, 1);
    // vt[b][d][t] = wvt[d][:] . h[b*T+t][:]
    hgemm<0,0><<<GRID_P, NT, SMEM_B>>>(p_wvt, p_h, p_vt, nullptr, nullptr,
                                       D_, D_, D_, T_, 0, (size_t)T_*D_, (size_t)D_*T_,
                                       16, 8, 4);
    // scores (pre-scaled q): lower triangle only
    hgemm<0,1><<<GRID_P, NT, SMEM_B>>>(p_qk, p_qk + 1024, p_s, nullptr, nullptr,
                                       2048, 2048, D_, T_,
                                       (size_t)T_*2048, (size_t)T_*2048, (size_t)T_*T_,
                                       16, 16, 4);
    softmax_kernel<<<M_, 256>>>(p_s);
    // y = half(P @ V^T + x)  (cost-sorted schedule, fp32 resid in, half out)
    hgemm<3,2><<<GRID_P, NT, SMEM_B>>>(p_s, p_vt, p_y, nullptr, x,
                                       T_, T_, T_, D_,
                                       (size_t)T_*T_, (size_t)D_*T_, (size_t)T_*D_,
                                       8, 16, 4);
    ln_half_kernel<<<M_, 256>>>(p_y, g2, be2, p_h2);
    hgemm<1,0><<<GRID_P, NT, SMEM_B>>>(p_h2, p_w1t, p_m1, b1, nullptr,
                                       D_, D_, D_, D_, 0, 0, 0, 8, 64, 1);
    // out = m1 @ W2 + b2 + y (half resid)
    hgemm<4,0><<<GRID_P, NT, SMEM_B>>>(p_m1, p_w2t, out, b2, p_y,
                                       D_, D_, D_, D_, 0, 0, 0, 8, 64, 1);
}